// round 16
// baseline (speedup 1.0000x reference)
#include <cuda_runtime.h>
#include <cstdint>

// LatticeSnake: B=32, L=512, W=9. Output [B, L, 9,9,9, 1] fp32 (48 MB).
// Doubled walk coords (the 2(L-1) grid offset cancels):
//   residue j:   p = 2*idx[j],         v = acids[j]*mask[j]
//   midpoint k:  p = idx[k]+idx[k+1],  v = (acids[k]+acids[k+1]+1)*mask[k+1]
//   voxel (i,r): value = sum of points at p == 2*idx[i] + r - 4
//
// R16 = R12 (best: dense grid-gather, R=8, NT=128, plain launches) with the
// gather stores VECTORIZED via a precomputed offset table:
//   window w's output starts (w mod 4) elems off 16B alignment, so with
//   phase a=(-w)&3 the elems r=a+4k (k<181) are aligned float4 groups.
//   off4[a][k] (724 int4, 11.6KB smem; window-independent since off(r) only
//   depends on sy,sz) gives the 4 grid cells per group. Gather round =
//   LDS.128 + 4x LDS.32 + ONE STG.128 (22cyc/4elems vs 28 scalar), no
//   per-element rollover ALU (R9's failure mode). 5 leftover elems/window
//   handled scalar. Table build overlaps the scan phase; still 2 barriers.

#define LS_L    512
#define LS_W    9
#define LS_W3   729
#define LS_R    8                // windows per K2 CTA
#define LS_NT   128
#define LS_NG   (LS_L / LS_R)    // 64 groups per batch
#define LS_MP   1024             // padded point count per batch
#define GRID_F  2560             // >= worst-case vol 15*13*13 = 2535
#define NGRP    181              // aligned float4 groups per window

__device__ int4 g_points[64 * LS_MP];        // px,py,pz,value_bits
__device__ int  g_meta[64 * LS_NG * 16];     // per group: bbox(6) + base[8]

// ---------------- Kernel 1: points + per-group meta (as R12) ----------------
__global__ __launch_bounds__(512)
void ls_prep_kernel(const float* __restrict__ acids,
                    const float* __restrict__ mask,
                    const int*   __restrict__ idx)
{
    __shared__ alignas(16) int   sidx[LS_L * 3];
    __shared__ alignas(16) float sA[LS_L];
    __shared__ alignas(16) float sM[LS_L];

    const int b   = blockIdx.x;
    const int tid = threadIdx.x;
    const int*   gi = idx   + (size_t)b * LS_L * 3;
    const float* ga = acids + (size_t)b * LS_L;
    const float* gm = mask  + (size_t)b * LS_L;

    {
        const int4* gi4 = reinterpret_cast<const int4*>(gi);
        int4* s4 = reinterpret_cast<int4*>(sidx);
        for (int e = tid; e < (LS_L * 3) / 4; e += 512) s4[e] = gi4[e];
        const float4* ga4 = reinterpret_cast<const float4*>(ga);
        const float4* gm4 = reinterpret_cast<const float4*>(gm);
        float4* a4 = reinterpret_cast<float4*>(sA);
        float4* m4 = reinterpret_cast<float4*>(sM);
        if (tid < LS_L / 4) { a4[tid] = ga4[tid]; m4[tid] = gm4[tid]; }
    }
    __syncthreads();

    int4* gp = g_points + b * LS_MP;

    // residues
    {
        const int jj = 3 * tid;
        gp[tid] = make_int4(2 * sidx[jj + 0], 2 * sidx[jj + 1],
                            2 * sidx[jj + 2],
                            __float_as_int(sA[tid] * sM[tid]));
    }
    // midpoints + sentinel at slot 1023
    {
        const int j = tid + LS_L;
        if (tid < LS_L - 1) {
            const int jj = 3 * tid;
            gp[j] = make_int4(sidx[jj + 0] + sidx[jj + 3],
                              sidx[jj + 1] + sidx[jj + 4],
                              sidx[jj + 2] + sidx[jj + 5],
                              __float_as_int((sA[tid] + sA[tid + 1] + 1.0f)
                                             * sM[tid + 1]));
        } else if (tid == LS_L - 1) {
            gp[j] = make_int4(1 << 28, 1 << 28, 1 << 28, 0);  // sentinel
        }
    }

    // per-group meta
    {
        const int g  = tid >> 3;
        const int r  = tid & 7;
        const int jj = 3 * (g * LS_R + r);
        const int cx = 2 * sidx[jj + 0];
        const int cy = 2 * sidx[jj + 1];
        const int cz = 2 * sidx[jj + 2];
        int xmin = cx, xmax = cx, ymin = cy, ymax = cy, zmin = cz, zmax = cz;
        #pragma unroll
        for (int d = 4; d >= 1; d >>= 1) {   // segmented reduce over 8 lanes
            xmin = min(xmin, __shfl_xor_sync(0xffffffffu, xmin, d));
            xmax = max(xmax, __shfl_xor_sync(0xffffffffu, xmax, d));
            ymin = min(ymin, __shfl_xor_sync(0xffffffffu, ymin, d));
            ymax = max(ymax, __shfl_xor_sync(0xffffffffu, ymax, d));
            zmin = min(zmin, __shfl_xor_sync(0xffffffffu, zmin, d));
            zmax = max(zmax, __shfl_xor_sync(0xffffffffu, zmax, d));
        }
        const int syv = ymax - ymin + 9;
        const int szv = zmax - zmin + 9;
        int* m = g_meta + (b * LS_NG + g) * 16;
        m[6 + r] = ((cx - xmin) * syv + (cy - ymin)) * szv + (cz - zmin);
        if (r == 0) {
            m[0] = xmin - 4; m[1] = ymin - 4; m[2] = zmin - 4;
            m[3] = xmax - xmin + 9; m[4] = syv; m[5] = szv;
        }
    }
}

// ---------------- Kernel 2: main (grid gather, vectorized stores) ----------
__global__ __launch_bounds__(LS_NT, 10)
void lattice_snake_kernel(float* __restrict__ out)
{
    __shared__ alignas(16) float grid[GRID_F];   // 10240 B
    __shared__ alignas(16) int4  off4[4 * NGRP]; // 11584 B
    __shared__ int sMeta[16];                    // bbox(6) + base[8]

    const int b   = blockIdx.x >> 6;            // / LS_NG
    const int g   = blockIdx.x & (LS_NG - 1);
    const int tid = threadIdx.x;

    const int4* gp = g_points + b * LS_MP;
    float* gout = out + (size_t)(b * LS_L + g * LS_R) * LS_W3;

    // meta load (overlaps zeroing)
    if (tid < 14) sMeta[tid] = g_meta[(b * LS_NG + g) * 16 + tid];

    // ---- zero grid (640 float4) ----
    {
        float4* g4 = reinterpret_cast<float4*>(grid);
        const float4 z = make_float4(0.f, 0.f, 0.f, 0.f);
        #pragma unroll
        for (int e = tid; e < GRID_F / 4; e += LS_NT) g4[e] = z;
    }
    __syncthreads();

    const int gxl = sMeta[0], gyl = sMeta[1], gzl = sMeta[2];
    const int sx  = sMeta[3], sy  = sMeta[4], sz  = sMeta[5];

    // ---- build off4 table (ALU+STS; overlaps the scan's LDG latency) ----
    for (int e = tid; e < 4 * NGRP; e += LS_NT) {
        const int a = e / NGRP;
        const int k = e - a * NGRP;
        int r  = a + 4 * k;                  // first elem of the group
        int rx = r / 81;
        int rem = r - rx * 81;
        int ry = rem / 9;
        int rz = rem - ry * 9;
        int off = (rx * sy + ry) * sz + rz;
        int4 o;
        o.x = off;
        #pragma unroll
        for (int q = 1; q < 4; q++) {
            rz++; off++;
            if (rz == LS_W) {
                rz = 0; ry++; off += sz - LS_W;
                if (ry == LS_W) { ry = 0; rx++; off += (sy - LS_W) * sz; }
            }
            if (q == 1) o.y = off; else if (q == 2) o.z = off; else o.w = off;
        }
        off4[e] = o;
    }

    // ---- scan 1024 packed points; 8 coalesced LDG.128 rounds ----
    #pragma unroll
    for (int rnd = 0; rnd < LS_MP / LS_NT; rnd++) {
        const int4 p = gp[rnd * LS_NT + tid];
        const unsigned ux = (unsigned)(p.x - gxl);
        const unsigned uy = (unsigned)(p.y - gyl);
        const unsigned uz = (unsigned)(p.z - gzl);
        if (ux < (unsigned)sx && uy < (unsigned)sy && uz < (unsigned)sz)
            atomicAdd(&grid[(ux * sy + uy) * sz + uz], __int_as_float(p.w));
    }
    __syncthreads();   // grid + off4 complete

    // ---- gather: per group LDS.128(off4) + 4 LDS.32 + one STG.128 ----
    #pragma unroll
    for (int w = 0; w < LS_R; w++) {
        const int a  = (-w) & 3;                 // alignment phase
        const int Aw = sMeta[6 + w];             // broadcast LDS
        float* gw = gout + w * LS_W3 + a;        // 16B-aligned base
        const int4* tab = off4 + a * NGRP;
        for (int k = tid; k < NGRP; k += LS_NT) {
            const int4 o = tab[k];
            float4 v;
            v.x = grid[Aw + o.x];
            v.y = grid[Aw + o.y];
            v.z = grid[Aw + o.z];
            v.w = grid[Aw + o.w];
            *reinterpret_cast<float4*>(gw + 4 * k) = v;
        }
    }
    // leftovers: 5 scalar elems per window (r < a, and r in [a+724, 728])
    if (tid < 5 * LS_R) {
        const int w = tid / 5;
        const int i = tid - 5 * w;
        const int a = (-w) & 3;
        const int r = (i < a) ? i : 724 + i;
        const int rx = r / 81;
        const int rem = r - rx * 81;
        const int ry = rem / 9;
        const int rz = rem - ry * 9;
        gout[w * LS_W3 + r] = grid[sMeta[6 + w] + (rx * sy + ry) * sz + rz];
    }
}

extern "C" void kernel_launch(void* const* d_in, const int* in_sizes, int n_in,
                              void* d_out, int out_size)
{
    const float* acids = (const float*)d_in[0];   // [B, L]
    const float* mask  = (const float*)d_in[1];   // [B, L]
    const int*   idx   = (const int*)  d_in[2];   // [B, L, 3]
    float*       out   = (float*)d_out;           // [B, L, 9,9,9, 1]

    const int nB = in_sizes[0] / LS_L;            // 32
    ls_prep_kernel<<<nB, 512>>>(acids, mask, idx);
    lattice_snake_kernel<<<nB * LS_NG, LS_NT>>>(out);
}

// round 17
// speedup vs baseline: 1.1081x; 1.1081x over previous
#include <cuda_runtime.h>
#include <cstdint>

// LatticeSnake: B=32, L=512, W=9. Output [B, L, 9,9,9, 1] fp32 (48 MB).
// Doubled walk coords (the 2(L-1) grid offset cancels):
//   residue j:   p = 2*idx[j],         v = acids[j]*mask[j]
//   midpoint k:  p = idx[k]+idx[k+1],  v = (acids[k]+acids[k+1]+1)*mask[k+1]
//   voxel (i,r): value = sum of points at p == 2*idx[i] + r - 4
//
// R17 = R12 dataflow (dense grid-gather, R=8, NT=128 — best: K2 14.37us),
// with ILP-focused micro-opts only:
//   - __launch_bounds__(128,12): 42-reg budget; gather explicitly batches
//     12 grid LDS (2 windows) into regs before 12 STGs -> deeper LSU
//     pipelining per warp (R12's 32-reg cap forced short LDS->STG batches)
//   - __stcs streaming stores (write-once output, evict-first L2)
//   - GRID_F padded to 2816 so speculative ro[5] loads need no guard
//   - K1 parallelized 4x (128 CTAs x 128 thr, quarter-batch each)

#define LS_L    512
#define LS_W    9
#define LS_W3   729
#define LS_R    8                // windows per K2 CTA
#define LS_NT   128
#define LS_NG   (LS_L / LS_R)    // 64 groups per batch
#define LS_MP   1024             // padded point count per batch
#define GRID_F  2816             // vol<=2535; pad for unguarded ro[5] loads

__device__ int4 g_points[64 * LS_MP];        // px,py,pz,value_bits
__device__ int  g_meta[64 * LS_NG * 16];     // per group: bbox(6) + base[8]

// ---------------- Kernel 1: points + per-group meta (4x parallel) ----------
__global__ __launch_bounds__(128)
void ls_prep_kernel(const float* __restrict__ acids,
                    const float* __restrict__ mask,
                    const int*   __restrict__ idx)
{
    __shared__ int   sidx[129 * 3];
    __shared__ float sA[129];
    __shared__ float sM[129];

    const int b   = blockIdx.x >> 2;
    const int q   = blockIdx.x & 3;
    const int r0  = q * 128;
    const int tid = threadIdx.x;

    const int*   gi = idx   + ((size_t)b * LS_L + r0) * 3;
    const float* ga = acids + (size_t)b * LS_L + r0;
    const float* gm = mask  + (size_t)b * LS_L + r0;

    const int nC = (q < 3) ? 129 : 128;
    for (int e = tid; e < nC * 3; e += 128) sidx[e] = gi[e];
    for (int e = tid; e < nC;     e += 128) { sA[e] = ga[e]; sM[e] = gm[e]; }
    __syncthreads();

    const int jj = 3 * tid;

    // residue point
    g_points[b * LS_MP + r0 + tid] =
        make_int4(2 * sidx[jj + 0], 2 * sidx[jj + 1], 2 * sidx[jj + 2],
                  __float_as_int(sA[tid] * sM[tid]));

    // midpoint (+ sentinel at global slot 1023)
    const int mi = b * LS_MP + LS_L + r0 + tid;
    if (q < 3 || tid < 127) {
        g_points[mi] = make_int4(sidx[jj + 0] + sidx[jj + 3],
                                 sidx[jj + 1] + sidx[jj + 4],
                                 sidx[jj + 2] + sidx[jj + 5],
                                 __float_as_int((sA[tid] + sA[tid + 1] + 1.0f)
                                                * sM[tid + 1]));
    } else {
        g_points[mi] = make_int4(1 << 28, 1 << 28, 1 << 28, 0);
    }

    // meta: 128 threads = 16 groups x 8 windows
    {
        const int gl  = tid >> 3;
        const int r   = tid & 7;
        const int cjj = 3 * (gl * 8 + r);
        const int cx = 2 * sidx[cjj + 0];
        const int cy = 2 * sidx[cjj + 1];
        const int cz = 2 * sidx[cjj + 2];
        int xmin = cx, xmax = cx, ymin = cy, ymax = cy, zmin = cz, zmax = cz;
        #pragma unroll
        for (int d = 4; d >= 1; d >>= 1) {   // segmented reduce over 8 lanes
            xmin = min(xmin, __shfl_xor_sync(0xffffffffu, xmin, d));
            xmax = max(xmax, __shfl_xor_sync(0xffffffffu, xmax, d));
            ymin = min(ymin, __shfl_xor_sync(0xffffffffu, ymin, d));
            ymax = max(ymax, __shfl_xor_sync(0xffffffffu, ymax, d));
            zmin = min(zmin, __shfl_xor_sync(0xffffffffu, zmin, d));
            zmax = max(zmax, __shfl_xor_sync(0xffffffffu, zmax, d));
        }
        const int syv = ymax - ymin + 9;
        const int szv = zmax - zmin + 9;
        int* m = g_meta + (b * LS_NG + q * 16 + gl) * 16;
        m[6 + r] = ((cx - xmin) * syv + (cy - ymin)) * szv + (cz - zmin);
        if (r == 0) {
            m[0] = xmin - 4; m[1] = ymin - 4; m[2] = zmin - 4;
            m[3] = xmax - xmin + 9; m[4] = syv; m[5] = szv;
        }
    }
}

// ---------------- Kernel 2: main (grid gather, ILP-batched) ----------------
__global__ __launch_bounds__(LS_NT, 12)
void lattice_snake_kernel(float* __restrict__ out)
{
    __shared__ alignas(16) float grid[GRID_F];   // 11264 B
    __shared__ int sMeta[16];                    // bbox(6) + base[8]

    const int b   = blockIdx.x >> 6;            // / LS_NG
    const int g   = blockIdx.x & (LS_NG - 1);
    const int tid = threadIdx.x;

    const int4* gp = g_points + b * LS_MP;
    float* gout = out + (size_t)(b * LS_L + g * LS_R) * LS_W3;

    // meta load (overlaps zeroing)
    if (tid < 14) sMeta[tid] = g_meta[(b * LS_NG + g) * 16 + tid];

    // ---- zero grid (704 float4) ----
    {
        float4* g4 = reinterpret_cast<float4*>(grid);
        const float4 z = make_float4(0.f, 0.f, 0.f, 0.f);
        for (int e = tid; e < GRID_F / 4; e += LS_NT) g4[e] = z;
    }
    __syncthreads();

    const int gxl = sMeta[0], gyl = sMeta[1], gzl = sMeta[2];
    const int sx  = sMeta[3], sy  = sMeta[4], sz  = sMeta[5];

    // ---- scan 1024 packed points; 8 coalesced LDG.128 rounds ----
    #pragma unroll
    for (int rnd = 0; rnd < LS_MP / LS_NT; rnd++) {
        const int4 p = gp[rnd * LS_NT + tid];
        const unsigned ux = (unsigned)(p.x - gxl);
        const unsigned uy = (unsigned)(p.y - gyl);
        const unsigned uz = (unsigned)(p.z - gzl);
        if (ux < (unsigned)sx && uy < (unsigned)sy && uz < (unsigned)sz)
            atomicAdd(&grid[(ux * sy + uy) * sz + uz], __int_as_float(p.w));
    }

    // per-thread voxel decomposition (6 rounds of 128 cover 729)
    const bool k5ok = tid < (LS_W3 - 5 * LS_NT);   // 89
    int ro[6];
    #pragma unroll
    for (int k = 0; k < 6; k++) {
        const int lin = tid + k * LS_NT;
        const int rx  = lin / 81;
        const int rem = lin - rx * 81;
        const int ry  = rem / 9;
        const int rz  = rem - ry * 9;
        ro[k] = (rx * sy + ry) * sz + rz;   // k=5 may exceed vol: GRID_F pads
    }
    __syncthreads();   // grid complete

    // ---- gather: 2 windows per block -> 12 LDS batched, then 12 STG ----
    #pragma unroll
    for (int wp = 0; wp < LS_R / 2; wp++) {
        const int A0 = sMeta[6 + 2 * wp];          // broadcast LDS
        const int A1 = sMeta[7 + 2 * wp];
        float v[12];
        #pragma unroll
        for (int k = 0; k < 6; k++) {              // 12 independent LDS
            v[k]     = grid[A0 + ro[k]];
            v[6 + k] = grid[A1 + ro[k]];
        }
        float* g0 = gout + (2 * wp) * LS_W3;
        float* g1 = gout + (2 * wp + 1) * LS_W3;
        #pragma unroll
        for (int k = 0; k < 5; k++) {              // streaming stores
            __stcs(&g0[tid + k * LS_NT], v[k]);
            __stcs(&g1[tid + k * LS_NT], v[6 + k]);
        }
        if (k5ok) {
            __stcs(&g0[tid + 5 * LS_NT], v[5]);
            __stcs(&g1[tid + 5 * LS_NT], v[11]);
        }
    }
}

extern "C" void kernel_launch(void* const* d_in, const int* in_sizes, int n_in,
                              void* d_out, int out_size)
{
    const float* acids = (const float*)d_in[0];   // [B, L]
    const float* mask  = (const float*)d_in[1];   // [B, L]
    const int*   idx   = (const int*)  d_in[2];   // [B, L, 3]
    float*       out   = (float*)d_out;           // [B, L, 9,9,9, 1]

    const int nB = in_sizes[0] / LS_L;            // 32
    ls_prep_kernel<<<nB * 4, 128>>>(acids, mask, idx);
    lattice_snake_kernel<<<nB * LS_NG, LS_NT>>>(out);
}